// round 11
// baseline (speedup 1.0000x reference)
#include <cuda_runtime.h>

typedef unsigned long long ull;
typedef unsigned int uint;

#define NTHREADS 512
#define RAYS 8
#define NBLOCKS 4096
#define B_TOTAL 32768
#define S_A 68     // stride for plain fp32 tiles (q,k,v,ao): frag loads conflict-free
#define S_I 136    // stride for interleaved (hi,lo) tiles: LDS.64 conflict-free
#define S_W 72     // stride for weight tiles: B-frag loads conflict-free

// smem layout (floats)
#define OFF_ACT 0                   // act interleaved 64x136 = 8704
#define OFF_X   8704                // ctx / FF1-out / latent-pong (il) = 8704
#define OFF_Q   17408               // f32 4352 each
#define OFF_K   21760
#define OFF_V   26112
#define OFF_AO  30464
#define OFF_W0  34816               // fp32 weights 64x72 = 4608 each
#define OFF_W1  39424
#define OFF_W2  44032
#define OFF_W3  48640
#define OFF_P   53248               // probs 8x64 (also cross-ctx rows)
#define SMEM_FLOATS (53248 + 512)   // 53760 floats = 215040 B
#define SMEM_BYTES (SMEM_FLOATS * 4)

struct Params {
  const float *query, *latent, *W1, *b1;
  const float *Wq, *bq, *Wk, *bk, *Wv, *bv, *Wo, *bo;
  const float *fW1, *fb1, *fW2, *fb2, *g1, *be1, *g2, *be2;
  const float *cWq, *cbq, *cWk, *cbk, *cWv, *cbv, *cWo, *cbo;
  const float *Wc, *bc, *Ws, *bs;
  float *o_color, *o_sigma, *o_out, *o_attn;
};

// ---------------- small helpers ----------------
__device__ __forceinline__ float tf32c(float x) {
  uint u;
  asm("cvt.rna.tf32.f32 %0, %1;" : "=r"(u) : "f"(x));
  return __uint_as_float(u);
}
__device__ __forceinline__ void split2(float x, uint& h, uint& l) {
  float hf = tf32c(x);
  h = __float_as_uint(hf);
  l = __float_as_uint(tf32c(x - hf));
}
__device__ __forceinline__ float2 split2f(float x) {
  float hf = tf32c(x);
  return make_float2(hf, tf32c(x - hf));
}
__device__ __forceinline__ ull ffma2(ull a, ull b, ull c) {
  ull d;
  asm("fma.rn.f32x2 %0, %1, %2, %3;" : "=l"(d) : "l"(a), "l"(b), "l"(c));
  return d;
}
__device__ __forceinline__ ull pack2(float lo, float hi) {
  ull d;
  asm("mov.b64 %0, {%1, %2};" : "=l"(d) : "f"(lo), "f"(hi));
  return d;
}
__device__ __forceinline__ float2 unpack2(ull v) {
  float lo, hi;
  asm("mov.b64 {%0, %1}, %2;" : "=f"(lo), "=f"(hi) : "l"(v));
  return make_float2(lo, hi);
}

__device__ __forceinline__ void mma8(float c[4], uint a0, uint a1, uint a2, uint a3,
                                     uint b0, uint b1) {
  asm("mma.sync.aligned.m16n8k8.row.col.f32.tf32.tf32.f32 "
      "{%0,%1,%2,%3},{%4,%5,%6,%7},{%8,%9},{%0,%1,%2,%3};"
      : "+f"(c[0]), "+f"(c[1]), "+f"(c[2]), "+f"(c[3])
      : "r"(a0), "r"(a1), "r"(a2), "r"(a3), "r"(b0), "r"(b1));
}

struct AF { uint h[4], l[4]; };
// load pre-split A fragment from interleaved tile: 4x LDS.64, zero ALU
__device__ __forceinline__ AF load_a(const float* __restrict__ A, int lane,
                                     int mt, int kk) {
  const int grp = lane >> 2, kq = lane & 3;
  const float* ar = A + (mt * 16 + grp) * S_I + (kk * 8 + kq) * 2;
  AF f;
  float2 x;
  x = *(const float2*)(ar);
  f.h[0] = __float_as_uint(x.x); f.l[0] = __float_as_uint(x.y);
  x = *(const float2*)(ar + 8 * S_I);
  f.h[1] = __float_as_uint(x.x); f.l[1] = __float_as_uint(x.y);
  x = *(const float2*)(ar + 8);
  f.h[2] = __float_as_uint(x.x); f.l[2] = __float_as_uint(x.y);
  x = *(const float2*)(ar + 8 * S_I + 8);
  f.h[3] = __float_as_uint(x.x); f.l[3] = __float_as_uint(x.y);
  return f;
}

// 3xTF32 k8 step (weights split per use)
__device__ __forceinline__ void mma3(float c[4], const AF& a, float w0, float w1) {
  uint b0h, b0l, b1h, b1l;
  split2(w0, b0h, b0l);
  split2(w1, b1h, b1l);
  mma8(c, a.h[0], a.h[1], a.h[2], a.h[3], b0h, b1h);
  mma8(c, a.l[0], a.l[1], a.l[2], a.l[3], b0h, b1h);
  mma8(c, a.h[0], a.h[1], a.h[2], a.h[3], b0l, b1l);
}

// Warp roles: mt = m-tile (16 rows), nq = n-quarter (16 cols)
__device__ __forceinline__ void gemm_acc(const float* __restrict__ A,
                                         const float* __restrict__ W,
                                         int lane, int mt, int nq, float c[2][4]) {
  const int kq = lane & 3, grp = lane >> 2;
  #pragma unroll
  for (int kk = 0; kk < 8; kk++) {
    AF a = load_a(A, lane, mt, kk);
    const float* wb = W + (kk * 8 + kq) * S_W + nq * 16 + grp;
    #pragma unroll
    for (int t = 0; t < 2; t++)
      mma3(c[t], a, wb[t * 8], wb[4 * S_W + t * 8]);
  }
}

__device__ __forceinline__ void gemm3_acc(const float* __restrict__ A,
                                          const float* __restrict__ W0,
                                          const float* __restrict__ W1,
                                          const float* __restrict__ W2,
                                          int lane, int mt, int nq,
                                          float c0[2][4], float c1[2][4],
                                          float c2[2][4]) {
  const int kq = lane & 3, grp = lane >> 2;
  #pragma unroll
  for (int kk = 0; kk < 8; kk++) {
    AF a = load_a(A, lane, mt, kk);
    const int off = (kk * 8 + kq) * S_W + nq * 16 + grp;
    const float* w0 = W0 + off;
    const float* w1 = W1 + off;
    const float* w2 = W2 + off;
    #pragma unroll
    for (int t = 0; t < 2; t++) {
      mma3(c0[t], a, w0[t * 8], w0[4 * S_W + t * 8]);
      mma3(c1[t], a, w1[t * 8], w1[4 * S_W + t * 8]);
      mma3(c2[t], a, w2[t * 8], w2[4 * S_W + t * 8]);
    }
  }
}

__device__ __forceinline__ void gemm2_acc(const float* __restrict__ A,
                                          const float* __restrict__ W0,
                                          const float* __restrict__ W1,
                                          int lane, int mt, int nq,
                                          float c0[2][4], float c1[2][4]) {
  const int kq = lane & 3, grp = lane >> 2;
  #pragma unroll
  for (int kk = 0; kk < 8; kk++) {
    AF a = load_a(A, lane, mt, kk);
    const int off = (kk * 8 + kq) * S_W + nq * 16 + grp;
    const float* w0 = W0 + off;
    const float* w1 = W1 + off;
    #pragma unroll
    for (int t = 0; t < 2; t++) {
      mma3(c0[t], a, w0[t * 8], w0[4 * S_W + t * 8]);
      mma3(c1[t], a, w1[t * 8], w1[4 * S_W + t * 8]);
    }
  }
}

// store C frags to PLAIN fp32 tile [64][S_A]; optional relu / interleaved-residual
__device__ __forceinline__ void store_c_f32(float* D, int lane, int mt, int nq,
                                            const float c[2][4], const float* bias,
                                            int do_relu, const float* resid_il) {
  const int grp = lane >> 2, kq = lane & 3;
  const int r = mt * 16 + grp;
  #pragma unroll
  for (int t = 0; t < 2; t++) {
    int col = nq * 16 + t * 8 + 2 * kq;
    float b0 = __ldg(bias + col), b1 = __ldg(bias + col + 1);
    float v0 = c[t][0] + b0, v1 = c[t][1] + b1;
    float v2 = c[t][2] + b0, v3 = c[t][3] + b1;
    if (resid_il) {
      float2 r0 = *(const float2*)(resid_il + r * S_I + col * 2);
      float2 r1 = *(const float2*)(resid_il + r * S_I + col * 2 + 2);
      float2 r2 = *(const float2*)(resid_il + (r + 8) * S_I + col * 2);
      float2 r3 = *(const float2*)(resid_il + (r + 8) * S_I + col * 2 + 2);
      v0 += r0.x + r0.y; v1 += r1.x + r1.y;
      v2 += r2.x + r2.y; v3 += r3.x + r3.y;
    }
    if (do_relu) {
      v0 = fmaxf(v0, 0.f); v1 = fmaxf(v1, 0.f);
      v2 = fmaxf(v2, 0.f); v3 = fmaxf(v3, 0.f);
    }
    *(float2*)(D + r * S_A + col) = make_float2(v0, v1);
    *(float2*)(D + (r + 8) * S_A + col) = make_float2(v2, v3);
  }
}

// store C frags pre-split to INTERLEAVED tile [64][S_I]
__device__ __forceinline__ void store_c_il(float* D, int lane, int mt, int nq,
                                           const float c[2][4], const float* bias,
                                           int do_relu) {
  const int grp = lane >> 2, kq = lane & 3;
  const int r = mt * 16 + grp;
  #pragma unroll
  for (int t = 0; t < 2; t++) {
    int col = nq * 16 + t * 8 + 2 * kq;
    float b0 = __ldg(bias + col), b1 = __ldg(bias + col + 1);
    float v0 = c[t][0] + b0, v1 = c[t][1] + b1;
    float v2 = c[t][2] + b0, v3 = c[t][3] + b1;
    if (do_relu) {
      v0 = fmaxf(v0, 0.f); v1 = fmaxf(v1, 0.f);
      v2 = fmaxf(v2, 0.f); v3 = fmaxf(v3, 0.f);
    }
    float2 s0 = split2f(v0), s1 = split2f(v1);
    float2 s2 = split2f(v2), s3 = split2f(v3);
    *(float4*)(D + r * S_I + col * 2) = make_float4(s0.x, s0.y, s1.x, s1.y);
    *(float4*)(D + (r + 8) * S_I + col * 2) = make_float4(s2.x, s2.y, s3.x, s3.y);
  }
}

__device__ __forceinline__ void stage_w(const float* __restrict__ src, int stride,
                                        float* __restrict__ dst, int tid) {
  #pragma unroll
  for (int it = 0; it < 2; it++) {
    int i = tid + it * NTHREADS;
    int d = i >> 4, j = (i & 15) * 4;
    *(float4*)(dst + d * S_W + j) = *(const float4*)(src + d * stride + j);
  }
}

// LayerNorm of 4 rows: s1 plain fp32 [S_A] (+ optional s2 interleaved), dst interleaved
__device__ __forceinline__ void ln4(const float* s1, const float* s2il,
                                    const float* g, const float* be,
                                    int lane, float* dstil) {
  float gg0 = __ldg(g + lane), gg1 = __ldg(g + lane + 32);
  float bb0 = __ldg(be + lane), bb1 = __ldg(be + lane + 32);
  #pragma unroll
  for (int s = 0; s < 4; s++) {
    float x0 = s1[s * S_A + lane];
    float x1 = s1[s * S_A + lane + 32];
    if (s2il) {
      float2 a0 = *(const float2*)(s2il + s * S_I + lane * 2);
      float2 a1 = *(const float2*)(s2il + s * S_I + (lane + 32) * 2);
      x0 += a0.x + a0.y;
      x1 += a1.x + a1.y;
    }
    float sum = x0 + x1;
    #pragma unroll
    for (int o = 16; o > 0; o >>= 1) sum += __shfl_xor_sync(0xffffffffu, sum, o);
    float mean = sum * 0.015625f;
    float d0 = x0 - mean, d1 = x1 - mean;
    float vs = d0 * d0 + d1 * d1;
    #pragma unroll
    for (int o = 16; o > 0; o >>= 1) vs += __shfl_xor_sync(0xffffffffu, vs, o);
    float rstd = rsqrtf(vs * 0.015625f + 1e-5f);
    float2 y0 = split2f(d0 * rstd * gg0 + bb0);
    float2 y1 = split2f(d1 * rstd * gg1 + bb1);
    *(float2*)(dstil + s * S_I + lane * 2) = y0;
    *(float2*)(dstil + s * S_I + (lane + 32) * 2) = y1;
  }
}

// stage a latent chunk pre-split into interleaved tile
#define STAGE_LAT(DST, KC)                                                     \
  do {                                                                         \
    _Pragma("unroll")                                                          \
    for (int it_ = 0; it_ < 2; it_++) {                                        \
      int i_ = tid + it_ * NTHREADS;                                           \
      int row_ = i_ >> 4, j_ = (i_ & 15) * 4;                                  \
      float4 v_ = *(const float4*)(p.latent + (size_t)(bbase + (row_ >> 3)) * 4096 + \
                                   (row_ & 7) * 512 + (KC) * 64 + j_);         \
      float2 a_ = split2f(v_.x), b_ = split2f(v_.y);                           \
      float2 c_ = split2f(v_.z), d_ = split2f(v_.w);                           \
      *(float4*)((DST) + row_ * S_I + j_ * 2) = make_float4(a_.x, a_.y, b_.x, b_.y); \
      *(float4*)((DST) + row_ * S_I + j_ * 2 + 4) = make_float4(c_.x, c_.y, d_.x, d_.y); \
    }                                                                          \
  } while (0)

__global__ void __launch_bounds__(NTHREADS, 1) rt_kernel(Params p) {
  extern __shared__ float sm[];
  const int tid = threadIdx.x;
  const int warp = tid >> 5, lane = tid & 31;
  const int mt = warp & 3, nq = warp >> 2;   // mma roles (4 x 4)
  const int ray = warp & 7, half = warp >> 3, rb = half * 4;  // scalar roles
  const int bbase = blockIdx.x * RAYS;
  const int b = bbase + ray;

  float* s_act = sm + OFF_ACT;   // interleaved
  float* s_x = sm + OFF_X;       // interleaved (ctx / FF1-out / latent-pong)
  float* s_q = sm + OFF_Q;       // fp32
  float* s_k = sm + OFF_K;
  float* s_v = sm + OFF_V;
  float* s_ao = sm + OFF_AO;
  float* s_w0 = sm + OFF_W0;
  float* s_w1 = sm + OFF_W1;
  float* s_w2 = sm + OFF_W2;
  float* s_w3 = sm + OFF_W3;
  float* my_p = sm + OFF_P + ray * 64;

  // ---------------- stage 0: act = relu(latent @ W1 + b1), K=512 ----------------
  {
    float* lat0 = s_act;   // ping-pong latent (il); final store also to s_act
    float* lat1 = s_x;
    stage_w(p.W1, 64, s_w0, tid);
    STAGE_LAT(lat0, 0);
    __syncthreads();
    float c[2][4] = {};
    for (int kc = 0; kc < 8; kc++) {
      const float* lb = (kc & 1) ? lat1 : lat0;
      const float* wb = (kc & 1) ? s_w1 : s_w0;
      if (kc < 7) {
        stage_w(p.W1 + (kc + 1) * 4096, 64, (kc & 1) ? s_w0 : s_w1, tid);
        STAGE_LAT((kc & 1) ? lat0 : lat1, kc + 1);
      }
      gemm_acc(lb, wb, lane, mt, nq, c);
      __syncthreads();
    }
    store_c_il(s_act, lane, mt, nq, c, p.b1, 1);
  }
  __syncthreads();

  // ---------------- 4 transformer layers ----------------
  for (int l = 0; l < 4; l++) {
    stage_w(p.Wq + l * 16384, 256, s_w0, tid);
    stage_w(p.Wk + l * 16384, 256, s_w1, tid);
    stage_w(p.Wv + l * 16384, 256, s_w2, tid);
    __syncthreads();

    float co[2][4] = {};   // out-proj accumulator across heads
    for (int h = 0; h < 4; h++) {
      // fused QKV (one A pass, tensor)
      {
        float cq[2][4] = {}, ck[2][4] = {}, cv[2][4] = {};
        gemm3_acc(s_act, s_w0, s_w1, s_w2, lane, mt, nq, cq, ck, cv);
        store_c_f32(s_q, lane, mt, nq, cq, p.bq + l * 256 + h * 64, 0, nullptr);
        store_c_f32(s_k, lane, mt, nq, ck, p.bk + l * 256 + h * 64, 0, nullptr);
        store_c_f32(s_v, lane, mt, nq, cv, p.bv + l * 256 + h * 64, 0, nullptr);
      }
      __syncthreads();   // (A) QKV visible

      // stage next weights; LDG latency overlapped by attention below
      stage_w(p.Wo + l * 16384 + h * 4096, 64, s_w3, tid);
      if (h < 3) {
        stage_w(p.Wq + l * 16384 + (h + 1) * 64, 256, s_w0, tid);
        stage_w(p.Wk + l * 16384 + (h + 1) * 64, 256, s_w1, tid);
        stage_w(p.Wv + l * 16384 + (h + 1) * 64, 256, s_w2, tid);
      } else {
        stage_w(p.fW1 + l * 4096, 64, s_w0, tid);
        stage_w(p.fW2 + l * 4096, 64, s_w1, tid);
      }

      // ---- attention (scalar fp32): warp pair per ray, 4 q-rows each ----
      {
        const float* qb = s_q + ray * 8 * S_A;
        const float* kb = s_k + ray * 8 * S_A;
        const float* vb = s_v + ray * 8 * S_A;
        int idx = half * 32 + lane;
        int qi = idx >> 3, ki = idx & 7;
        const float* qr = qb + qi * S_A;
        const float* kr = kb + ki * S_A;
        ull acc = pack2(0.f, 0.f);
        #pragma unroll
        for (int j = 0; j < 64; j += 4) {
          ulonglong2 qq = *(const ulonglong2*)(qr + j);
          ulonglong2 kk2 = *(const ulonglong2*)(kr + j);
          acc = ffma2(qq.x, kk2.x, acc);
          acc = ffma2(qq.y, kk2.y, acc);
        }
        float2 t = unpack2(acc);
        float sc = (t.x + t.y) * 0.125f;
        float m = sc;
        m = fmaxf(m, __shfl_xor_sync(0xffffffffu, m, 1));
        m = fmaxf(m, __shfl_xor_sync(0xffffffffu, m, 2));
        m = fmaxf(m, __shfl_xor_sync(0xffffffffu, m, 4));
        float e = __expf(sc - m);
        float se = e;
        se += __shfl_xor_sync(0xffffffffu, se, 1);
        se += __shfl_xor_sync(0xffffffffu, se, 2);
        se += __shfl_xor_sync(0xffffffffu, se, 4);
        float pr = __fdividef(e, se);
        my_p[idx] = pr;
        p.o_attn[(size_t)b * 1024 + (size_t)l * 256 + h * 64 + idx] = pr;
        __syncwarp();
        // ctx rows rb..rb+3 = P @ V; store pre-split into x_il
        float cx[8];
        #pragma unroll
        for (int i = 0; i < 8; i++) cx[i] = 0.f;
        #pragma unroll
        for (int kj = 0; kj < 8; kj++) {
          float vx = vb[kj * S_A + lane];
          float vy = vb[kj * S_A + lane + 32];
          #pragma unroll
          for (int ql = 0; ql < 4; ql++) {
            float pk = my_p[(rb + ql) * 8 + kj];
            cx[2 * ql] = fmaf(pk, vx, cx[2 * ql]);
            cx[2 * ql + 1] = fmaf(pk, vy, cx[2 * ql + 1]);
          }
        }
        float* cr = s_x + (ray * 8 + rb) * S_I;
        #pragma unroll
        for (int ql = 0; ql < 4; ql++) {
          *(float2*)(cr + ql * S_I + lane * 2) = split2f(cx[2 * ql]);
          *(float2*)(cr + ql * S_I + (lane + 32) * 2) = split2f(cx[2 * ql + 1]);
        }
      }
      __syncthreads();   // (B) ctx + staged weights visible

      // out-proj: co += ctx @ Wo_h (tensor)
      gemm_acc(s_x, s_w3, lane, mt, nq, co);
      // no sync: next head's stores hit q/k/v; x/w3 readers precede sync-A(h+1)
    }  // heads

    store_c_f32(s_ao, lane, mt, nq, co, p.bo + l * 64, 0, nullptr);
    __syncthreads();
    // LN1: act = LN(ao + act)
    ln4(s_ao + (ray * 8 + rb) * S_A, s_act + (ray * 8 + rb) * S_I,
        p.g1 + l * 64, p.be1 + l * 64, lane, s_act + (ray * 8 + rb) * S_I);
    __syncthreads();
    // FF1 (w0 = fW1 staged during h==3) -> x_il with relu
    {
      float c[2][4] = {};
      gemm_acc(s_act, s_w0, lane, mt, nq, c);
      store_c_il(s_x, lane, mt, nq, c, p.fb1 + l * 64, 1);
    }
    __syncthreads();
    // FF2 + residual -> ao (fp32)
    {
      float c[2][4] = {};
      gemm_acc(s_x, s_w1, lane, mt, nq, c);
      store_c_f32(s_ao, lane, mt, nq, c, p.fb2 + l * 64, 0, s_act);
    }
    __syncthreads();
    // LN2: act = LN(ao)
    ln4(s_ao + (ray * 8 + rb) * S_A, nullptr,
        p.g2 + l * 64, p.be2 + l * 64, lane, s_act + (ray * 8 + rb) * S_I);
    __syncthreads();
  }  // layers

  // ---------------- sigma & out ----------------
  {
    const float* ar = s_act + ray * 8 * S_I;
    if (half == 0) {
      float m0 = -1e30f, m1 = -1e30f;
      #pragma unroll
      for (int s = 0; s < 8; s++) {
        float2 a0 = *(const float2*)(ar + s * S_I + lane * 2);
        float2 a1 = *(const float2*)(ar + s * S_I + (lane + 32) * 2);
        m0 = fmaxf(m0, a0.x + a0.y);
        m1 = fmaxf(m1, a1.x + a1.y);
      }
      float part = m0 * __ldg(p.Ws + lane) + m1 * __ldg(p.Ws + lane + 32);
      #pragma unroll
      for (int o = 16; o > 0; o >>= 1) part += __shfl_xor_sync(0xffffffffu, part, o);
      if (lane == 0) p.o_sigma[b] = part + __ldg(p.bs);
    }
    #pragma unroll
    for (int s = 0; s < 4; s++) {
      float2 a0 = *(const float2*)(ar + (rb + s) * S_I + lane * 2);
      float2 a1 = *(const float2*)(ar + (rb + s) * S_I + (lane + 32) * 2);
      p.o_out[(size_t)b * 512 + (rb + s) * 64 + lane] = a0.x + a0.y;
      p.o_out[(size_t)b * 512 + (rb + s) * 64 + lane + 32] = a1.x + a1.y;
    }
  }

  // ---------------- cross attention + color ----------------
  float* qr = s_ao + ray * S_A;  // query row (fp32)
  if (half == 0) {
    qr[lane] = p.query[(size_t)b * 64 + lane];
    qr[lane + 32] = p.query[(size_t)b * 64 + lane + 32];
  }

  float ca0 = 0.f, ca1 = 0.f;
  for (int h = 0; h < 4; h++) {
    __syncthreads();   // protect weight bufs from previous head's scalar readers
    stage_w(p.cWk + h * 64, 256, s_w0, tid);
    stage_w(p.cWv + h * 64, 256, s_w1, tid);
    stage_w(p.cWq + h * 64, 256, s_w3, tid);
    stage_w(p.cWo + h * 4096, 64, s_w2, tid);
    __syncthreads();
    // fused cK, cV gemms (tensor) -> fp32 tiles
    {
      float ck[2][4] = {}, cv[2][4] = {};
      gemm2_acc(s_act, s_w0, s_w1, lane, mt, nq, ck, cv);
      store_c_f32(s_k, lane, mt, nq, ck, p.cbk + h * 64, 0, nullptr);
      store_c_f32(s_v, lane, mt, nq, cv, p.cbv + h * 64, 0, nullptr);
    }
    __syncthreads();
    // per-ray scalar on warps 0-7 (cross ctx row lives in my_p)
    if (half == 0) {
      float cq0 = __ldg(p.cbq + h * 64 + lane);
      float cq1 = __ldg(p.cbq + h * 64 + lane + 32);
      #pragma unroll 8
      for (int k = 0; k < 64; k++) {
        float a = qr[k];
        cq0 = fmaf(a, s_w3[k * S_W + lane], cq0);
        cq1 = fmaf(a, s_w3[k * S_W + lane + 32], cq1);
      }
      const float* kb = s_k + ray * 8 * S_A;
      const float* vb = s_v + ray * 8 * S_A;
      float e[8];
      #pragma unroll
      for (int k = 0; k < 8; k++) {
        float pk = cq0 * kb[k * S_A + lane] + cq1 * kb[k * S_A + lane + 32];
        #pragma unroll
        for (int o = 16; o > 0; o >>= 1) pk += __shfl_xor_sync(0xffffffffu, pk, o);
        e[k] = pk * 0.125f;
      }
      float mm = e[0];
      #pragma unroll
      for (int k = 1; k < 8; k++) mm = fmaxf(mm, e[k]);
      float prb[8], sum = 0.f;
      #pragma unroll
      for (int k = 0; k < 8; k++) { prb[k] = __expf(e[k] - mm); sum += prb[k]; }
      float inv = __fdividef(1.f, sum);
      float cx0 = 0.f, cx1 = 0.f;
      #pragma unroll
      for (int k = 0; k < 8; k++) {
        float pk = prb[k] * inv;
        cx0 = fmaf(pk, vb[k * S_A + lane], cx0);
        cx1 = fmaf(pk, vb[k * S_A + lane + 32], cx1);
      }
      my_p[lane] = cx0;
      my_p[lane + 32] = cx1;
      __syncwarp();
      if (h == 0) { ca0 = __ldg(p.cbo + lane); ca1 = __ldg(p.cbo + lane + 32); }
      #pragma unroll 8
      for (int k = 0; k < 64; k++) {
        float a = my_p[k];
        ca0 = fmaf(a, s_w2[k * S_W + lane], ca0);
        ca1 = fmaf(a, s_w2[k * S_W + lane + 32], ca1);
      }
    }
  }

  // color = relu(ca) @ Wc + bc (warps 0-7)
  if (half == 0) {
    float r0 = fmaxf(ca0, 0.f), r1 = fmaxf(ca1, 0.f);
    #pragma unroll
    for (int t = 0; t < 3; t++) {
      float part = r0 * __ldg(p.Wc + lane * 3 + t) + r1 * __ldg(p.Wc + (lane + 32) * 3 + t);
      #pragma unroll
      for (int o = 16; o > 0; o >>= 1) part += __shfl_xor_sync(0xffffffffu, part, o);
      if (lane == 0) p.o_color[(size_t)b * 3 + t] = part + __ldg(p.bc + t);
    }
  }
}

extern "C" void kernel_launch(void* const* d_in, const int* in_sizes, int n_in,
                              void* d_out, int out_size) {
  Params p;
  p.query = (const float*)d_in[0];
  p.latent = (const float*)d_in[1];
  p.W1 = (const float*)d_in[2];
  p.b1 = (const float*)d_in[3];
  p.Wq = (const float*)d_in[4];
  p.bq = (const float*)d_in[5];
  p.Wk = (const float*)d_in[6];
  p.bk = (const float*)d_in[7];
  p.Wv = (const float*)d_in[8];
  p.bv = (const float*)d_in[9];
  p.Wo = (const float*)d_in[10];
  p.bo = (const float*)d_in[11];
  p.fW1 = (const float*)d_in[12];
  p.fb1 = (const float*)d_in[13];
  p.fW2 = (const float*)d_in[14];
  p.fb2 = (const float*)d_in[15];
  p.g1 = (const float*)d_in[16];
  p.be1 = (const float*)d_in[17];
  p.g2 = (const float*)d_in[18];
  p.be2 = (const float*)d_in[19];
  p.cWq = (const float*)d_in[20];
  p.cbq = (const float*)d_in[21];
  p.cWk = (const float*)d_in[22];
  p.cbk = (const float*)d_in[23];
  p.cWv = (const float*)d_in[24];
  p.cbv = (const float*)d_in[25];
  p.cWo = (const float*)d_in[26];
  p.cbo = (const float*)d_in[27];
  p.Wc = (const float*)d_in[28];
  p.bc = (const float*)d_in[29];
  p.Ws = (const float*)d_in[30];
  p.bs = (const float*)d_in[31];

  float* o = (float*)d_out;
  p.o_color = o;                                    // [B,1,3]
  p.o_sigma = o + (size_t)B_TOTAL * 3;              // [B,1]
  p.o_out = o + (size_t)B_TOTAL * 4;                // [B,8,64]
  p.o_attn = o + (size_t)B_TOTAL * 4 + (size_t)B_TOTAL * 512;  // [B,4,4,8,8]

  cudaFuncSetAttribute(rt_kernel, cudaFuncAttributeMaxDynamicSharedMemorySize,
                       SMEM_BYTES);
  rt_kernel<<<NBLOCKS, NTHREADS, SMEM_BYTES>>>(p);
}

// round 12
// speedup vs baseline: 1.0658x; 1.0658x over previous
#include <cuda_runtime.h>

typedef unsigned long long ull;
typedef unsigned int uint;

#define NTHREADS 512
#define RAYS 8
#define NBLOCKS 4096
#define B_TOTAL 32768
#define S_A 68     // stride for plain fp32 tiles: frag loads conflict-free
#define S_WI 136   // stride for interleaved (hi,lo) weight tiles: LDS.64 conflict-free

// smem layout (floats)
#define OFF_ACT 0                   // act fp32 64x68 = 4352
#define OFF_Q   4352                // q / ctx overlay / FF1-out (fp32)
#define OFF_K   8704
#define OFF_V   13056
#define OFF_AO  17408
#define OFF_W0  21760               // interleaved weights 64x136 = 8704 each
#define OFF_W1  30464
#define OFF_W2  39168
#define OFF_W3  47872
#define OFF_P   56576               // probs 8x64
#define SMEM_FLOATS (56576 + 512)   // 57088 floats = 228352 B (<= 227KB limit)
#define SMEM_BYTES (SMEM_FLOATS * 4)

struct Params {
  const float *query, *latent, *W1, *b1;
  const float *Wq, *bq, *Wk, *bk, *Wv, *bv, *Wo, *bo;
  const float *fW1, *fb1, *fW2, *fb2, *g1, *be1, *g2, *be2;
  const float *cWq, *cbq, *cWk, *cbk, *cWv, *cbv, *cWo, *cbo;
  const float *Wc, *bc, *Ws, *bs;
  float *o_color, *o_sigma, *o_out, *o_attn;
};

// ---------------- small helpers ----------------
__device__ __forceinline__ float tf32c(float x) {
  uint u;
  asm("cvt.rna.tf32.f32 %0, %1;" : "=r"(u) : "f"(x));
  return __uint_as_float(u);
}
__device__ __forceinline__ void split2(float x, uint& h, uint& l) {
  float hf = tf32c(x);
  h = __float_as_uint(hf);
  l = __float_as_uint(tf32c(x - hf));
}
__device__ __forceinline__ float2 split2f(float x) {
  float hf = tf32c(x);
  return make_float2(hf, tf32c(x - hf));
}
__device__ __forceinline__ ull ffma2(ull a, ull b, ull c) {
  ull d;
  asm("fma.rn.f32x2 %0, %1, %2, %3;" : "=l"(d) : "l"(a), "l"(b), "l"(c));
  return d;
}
__device__ __forceinline__ ull pack2(float lo, float hi) {
  ull d;
  asm("mov.b64 %0, {%1, %2};" : "=l"(d) : "f"(lo), "f"(hi));
  return d;
}
__device__ __forceinline__ float2 unpack2(ull v) {
  float lo, hi;
  asm("mov.b64 {%0, %1}, %2;" : "=f"(lo), "=f"(hi) : "l"(v));
  return make_float2(lo, hi);
}

__device__ __forceinline__ void mma8(float c[4], uint a0, uint a1, uint a2, uint a3,
                                     uint b0, uint b1) {
  asm("mma.sync.aligned.m16n8k8.row.col.f32.tf32.tf32.f32 "
      "{%0,%1,%2,%3},{%4,%5,%6,%7},{%8,%9},{%0,%1,%2,%3};"
      : "+f"(c[0]), "+f"(c[1]), "+f"(c[2]), "+f"(c[3])
      : "r"(a0), "r"(a1), "r"(a2), "r"(a3), "r"(b0), "r"(b1));
}

struct AF { uint h[4], l[4]; };
// A fragment from fp32 tile, split in-loop (amortized across 2 n-tiles x 1-3 W)
__device__ __forceinline__ AF load_a(const float* __restrict__ A, int lane,
                                     int mt, int kk) {
  const int grp = lane >> 2, kq = lane & 3;
  const float* ar = A + (mt * 16 + grp) * S_A + kk * 8 + kq;
  AF f;
  split2(ar[0], f.h[0], f.l[0]);
  split2(ar[8 * S_A], f.h[1], f.l[1]);
  split2(ar[4], f.h[2], f.l[2]);
  split2(ar[8 * S_A + 4], f.h[3], f.l[3]);
  return f;
}

// 3xTF32 k8 step with PRE-SPLIT weights: w0p/w1p = (hi,lo) pairs, zero split ALU
__device__ __forceinline__ void mma3p(float c[4], const AF& a, float2 w0p, float2 w1p) {
  mma8(c, a.h[0], a.h[1], a.h[2], a.h[3],
       __float_as_uint(w0p.x), __float_as_uint(w1p.x));
  mma8(c, a.l[0], a.l[1], a.l[2], a.l[3],
       __float_as_uint(w0p.x), __float_as_uint(w1p.x));
  mma8(c, a.h[0], a.h[1], a.h[2], a.h[3],
       __float_as_uint(w0p.y), __float_as_uint(w1p.y));
}

// Warp roles: mt = m-tile (16 rows), nq = n-quarter (16 cols). W interleaved.
__device__ __forceinline__ void gemm_acc(const float* __restrict__ A,
                                         const float* __restrict__ W,
                                         int lane, int mt, int nq, float c[2][4]) {
  const int kq = lane & 3, grp = lane >> 2;
  #pragma unroll
  for (int kk = 0; kk < 8; kk++) {
    AF a = load_a(A, lane, mt, kk);
    const float* wb = W + (kk * 8 + kq) * S_WI + (nq * 16 + grp) * 2;
    #pragma unroll
    for (int t = 0; t < 2; t++) {
      float2 w0p = *(const float2*)(wb + t * 16);
      float2 w1p = *(const float2*)(wb + 4 * S_WI + t * 16);
      mma3p(c[t], a, w0p, w1p);
    }
  }
}

__device__ __forceinline__ void gemm3_acc(const float* __restrict__ A,
                                          const float* __restrict__ W0,
                                          const float* __restrict__ W1,
                                          const float* __restrict__ W2,
                                          int lane, int mt, int nq,
                                          float c0[2][4], float c1[2][4],
                                          float c2[2][4]) {
  const int kq = lane & 3, grp = lane >> 2;
  #pragma unroll
  for (int kk = 0; kk < 8; kk++) {
    AF a = load_a(A, lane, mt, kk);
    const int off = (kk * 8 + kq) * S_WI + (nq * 16 + grp) * 2;
    #pragma unroll
    for (int t = 0; t < 2; t++) {
      float2 w0p, w1p;
      w0p = *(const float2*)(W0 + off + t * 16);
      w1p = *(const float2*)(W0 + off + 4 * S_WI + t * 16);
      mma3p(c0[t], a, w0p, w1p);
      w0p = *(const float2*)(W1 + off + t * 16);
      w1p = *(const float2*)(W1 + off + 4 * S_WI + t * 16);
      mma3p(c1[t], a, w0p, w1p);
      w0p = *(const float2*)(W2 + off + t * 16);
      w1p = *(const float2*)(W2 + off + 4 * S_WI + t * 16);
      mma3p(c2[t], a, w0p, w1p);
    }
  }
}

__device__ __forceinline__ void gemm2_acc(const float* __restrict__ A,
                                          const float* __restrict__ W0,
                                          const float* __restrict__ W1,
                                          int lane, int mt, int nq,
                                          float c0[2][4], float c1[2][4]) {
  const int kq = lane & 3, grp = lane >> 2;
  #pragma unroll
  for (int kk = 0; kk < 8; kk++) {
    AF a = load_a(A, lane, mt, kk);
    const int off = (kk * 8 + kq) * S_WI + (nq * 16 + grp) * 2;
    #pragma unroll
    for (int t = 0; t < 2; t++) {
      float2 w0p, w1p;
      w0p = *(const float2*)(W0 + off + t * 16);
      w1p = *(const float2*)(W0 + off + 4 * S_WI + t * 16);
      mma3p(c0[t], a, w0p, w1p);
      w0p = *(const float2*)(W1 + off + t * 16);
      w1p = *(const float2*)(W1 + off + 4 * S_WI + t * 16);
      mma3p(c1[t], a, w0p, w1p);
    }
  }
}

// store C frags to plain fp32 tile [64][S_A]; optional relu / fp32 residual
__device__ __forceinline__ void store_c(float* D, int lane, int mt, int nq,
                                        const float c[2][4], const float* bias,
                                        int do_relu, const float* resid) {
  const int grp = lane >> 2, kq = lane & 3;
  const int r = mt * 16 + grp;
  #pragma unroll
  for (int t = 0; t < 2; t++) {
    int col = nq * 16 + t * 8 + 2 * kq;
    float b0 = __ldg(bias + col), b1 = __ldg(bias + col + 1);
    float v0 = c[t][0] + b0, v1 = c[t][1] + b1;
    float v2 = c[t][2] + b0, v3 = c[t][3] + b1;
    if (resid) {
      v0 += resid[r * S_A + col];
      v1 += resid[r * S_A + col + 1];
      v2 += resid[(r + 8) * S_A + col];
      v3 += resid[(r + 8) * S_A + col + 1];
    }
    if (do_relu) {
      v0 = fmaxf(v0, 0.f); v1 = fmaxf(v1, 0.f);
      v2 = fmaxf(v2, 0.f); v3 = fmaxf(v3, 0.f);
    }
    *(float2*)(D + r * S_A + col) = make_float2(v0, v1);
    *(float2*)(D + (r + 8) * S_A + col) = make_float2(v2, v3);
  }
}

// stage 64x64 weight block SPLIT into interleaved [64][S_WI] smem (split ONCE here)
__device__ __forceinline__ void stage_w_il(const float* __restrict__ src, int stride,
                                           float* __restrict__ dst, int tid) {
  #pragma unroll
  for (int it = 0; it < 2; it++) {
    int i = tid + it * NTHREADS;
    int d = i >> 4, j = (i & 15) * 4;
    float4 v = *(const float4*)(src + d * stride + j);
    float2 a = split2f(v.x), b = split2f(v.y);
    float2 c = split2f(v.z), e = split2f(v.w);
    *(float4*)(dst + d * S_WI + j * 2) = make_float4(a.x, a.y, b.x, b.y);
    *(float4*)(dst + d * S_WI + j * 2 + 4) = make_float4(c.x, c.y, e.x, e.y);
  }
}

// LayerNorm of 4 rows (all fp32)
__device__ __forceinline__ void ln4(const float* s1, const float* s2,
                                    const float* g, const float* be,
                                    int lane, float* dst) {
  float gg0 = __ldg(g + lane), gg1 = __ldg(g + lane + 32);
  float bb0 = __ldg(be + lane), bb1 = __ldg(be + lane + 32);
  #pragma unroll
  for (int s = 0; s < 4; s++) {
    float x0 = s1[s * S_A + lane];
    float x1 = s1[s * S_A + lane + 32];
    if (s2) { x0 += s2[s * S_A + lane]; x1 += s2[s * S_A + lane + 32]; }
    float sum = x0 + x1;
    #pragma unroll
    for (int o = 16; o > 0; o >>= 1) sum += __shfl_xor_sync(0xffffffffu, sum, o);
    float mean = sum * 0.015625f;
    float d0 = x0 - mean, d1 = x1 - mean;
    float vs = d0 * d0 + d1 * d1;
    #pragma unroll
    for (int o = 16; o > 0; o >>= 1) vs += __shfl_xor_sync(0xffffffffu, vs, o);
    float rstd = rsqrtf(vs * 0.015625f + 1e-5f);
    dst[s * S_A + lane] = d0 * rstd * gg0 + bb0;
    dst[s * S_A + lane + 32] = d1 * rstd * gg1 + bb1;
  }
}

#define STAGE_LAT(DST, KC)                                                     \
  do {                                                                         \
    _Pragma("unroll")                                                          \
    for (int it_ = 0; it_ < 2; it_++) {                                        \
      int i_ = tid + it_ * NTHREADS;                                           \
      int row_ = i_ >> 4, j_ = (i_ & 15) * 4;                                  \
      *(float4*)((DST) + row_ * S_A + j_) =                                    \
          *(const float4*)(p.latent + (size_t)(bbase + (row_ >> 3)) * 4096 +   \
                           (row_ & 7) * 512 + (KC) * 64 + j_);                 \
    }                                                                          \
  } while (0)

__global__ void __launch_bounds__(NTHREADS, 1) rt_kernel(Params p) {
  extern __shared__ float sm[];
  const int tid = threadIdx.x;
  const int warp = tid >> 5, lane = tid & 31;
  const int mt = warp & 3, nq = warp >> 2;   // mma roles (4 x 4)
  const int ray = warp & 7, half = warp >> 3, rb = half * 4;  // scalar roles
  const int bbase = blockIdx.x * RAYS;
  const int b = bbase + ray;

  float* s_act = sm + OFF_ACT;   // fp32
  float* s_q = sm + OFF_Q;       // fp32: q, then ctx overlay, then FF1-out
  float* s_k = sm + OFF_K;
  float* s_v = sm + OFF_V;
  float* s_ao = sm + OFF_AO;
  float* s_w0 = sm + OFF_W0;     // interleaved (hi,lo) weights
  float* s_w1 = sm + OFF_W1;
  float* s_w2 = sm + OFF_W2;
  float* s_w3 = sm + OFF_W3;
  float* my_p = sm + OFF_P + ray * 64;

  // ---------------- stage 0: act = relu(latent @ W1 + b1), K=512 ----------------
  {
    float* lat0 = s_q;     // fp32 latent ping-pong
    float* lat1 = s_k;
    stage_w_il(p.W1, 64, s_w0, tid);
    STAGE_LAT(lat0, 0);
    __syncthreads();
    float c[2][4] = {};
    for (int kc = 0; kc < 8; kc++) {
      const float* lb = (kc & 1) ? lat1 : lat0;
      const float* wb = (kc & 1) ? s_w1 : s_w0;
      if (kc < 7) {
        stage_w_il(p.W1 + (kc + 1) * 4096, 64, (kc & 1) ? s_w0 : s_w1, tid);
        STAGE_LAT((kc & 1) ? lat0 : lat1, kc + 1);
      }
      gemm_acc(lb, wb, lane, mt, nq, c);
      __syncthreads();
    }
    store_c(s_act, lane, mt, nq, c, p.b1, 1, nullptr);
  }
  __syncthreads();

  // ---------------- 4 transformer layers ----------------
  for (int l = 0; l < 4; l++) {
    stage_w_il(p.Wq + l * 16384, 256, s_w0, tid);
    stage_w_il(p.Wk + l * 16384, 256, s_w1, tid);
    stage_w_il(p.Wv + l * 16384, 256, s_w2, tid);
    __syncthreads();

    float co[2][4] = {};   // out-proj accumulator across heads
    for (int h = 0; h < 4; h++) {
      // fused QKV (one A pass, pre-split weights)
      {
        float cq[2][4] = {}, ck[2][4] = {}, cv[2][4] = {};
        gemm3_acc(s_act, s_w0, s_w1, s_w2, lane, mt, nq, cq, ck, cv);
        store_c(s_q, lane, mt, nq, cq, p.bq + l * 256 + h * 64, 0, nullptr);
        store_c(s_k, lane, mt, nq, ck, p.bk + l * 256 + h * 64, 0, nullptr);
        store_c(s_v, lane, mt, nq, cv, p.bv + l * 256 + h * 64, 0, nullptr);
      }
      __syncthreads();   // (A) QKV visible

      // stage next weights; LDG latency overlapped by attention below
      stage_w_il(p.Wo + l * 16384 + h * 4096, 64, s_w3, tid);
      if (h < 3) {
        stage_w_il(p.Wq + l * 16384 + (h + 1) * 64, 256, s_w0, tid);
        stage_w_il(p.Wk + l * 16384 + (h + 1) * 64, 256, s_w1, tid);
        stage_w_il(p.Wv + l * 16384 + (h + 1) * 64, 256, s_w2, tid);
      } else {
        stage_w_il(p.fW1 + l * 4096, 64, s_w0, tid);
        stage_w_il(p.fW2 + l * 4096, 64, s_w1, tid);
      }

      // ---- attention (scalar fp32): warp pair per ray, 4 q-rows each ----
      {
        const float* qb = s_q + ray * 8 * S_A;
        const float* kb = s_k + ray * 8 * S_A;
        const float* vb = s_v + ray * 8 * S_A;
        int idx = half * 32 + lane;
        int qi = idx >> 3, ki = idx & 7;
        const float* qr = qb + qi * S_A;
        const float* kr = kb + ki * S_A;
        ull acc = pack2(0.f, 0.f);
        #pragma unroll
        for (int j = 0; j < 64; j += 4) {
          ulonglong2 qq = *(const ulonglong2*)(qr + j);
          ulonglong2 kk2 = *(const ulonglong2*)(kr + j);
          acc = ffma2(qq.x, kk2.x, acc);
          acc = ffma2(qq.y, kk2.y, acc);
        }
        float2 t = unpack2(acc);
        float sc = (t.x + t.y) * 0.125f;
        float m = sc;
        m = fmaxf(m, __shfl_xor_sync(0xffffffffu, m, 1));
        m = fmaxf(m, __shfl_xor_sync(0xffffffffu, m, 2));
        m = fmaxf(m, __shfl_xor_sync(0xffffffffu, m, 4));
        float e = __expf(sc - m);
        float se = e;
        se += __shfl_xor_sync(0xffffffffu, se, 1);
        se += __shfl_xor_sync(0xffffffffu, se, 2);
        se += __shfl_xor_sync(0xffffffffu, se, 4);
        float pr = __fdividef(e, se);
        my_p[idx] = pr;
        p.o_attn[(size_t)b * 1024 + (size_t)l * 256 + h * 64 + idx] = pr;
        __syncwarp();
        // ctx rows rb..rb+3 = P @ V; ctx OVERLAYS q (own rows already consumed)
        float cx[8];
        #pragma unroll
        for (int i = 0; i < 8; i++) cx[i] = 0.f;
        #pragma unroll
        for (int kj = 0; kj < 8; kj++) {
          float vx = vb[kj * S_A + lane];
          float vy = vb[kj * S_A + lane + 32];
          #pragma unroll
          for (int ql = 0; ql < 4; ql++) {
            float pk = my_p[(rb + ql) * 8 + kj];
            cx[2 * ql] = fmaf(pk, vx, cx[2 * ql]);
            cx[2 * ql + 1] = fmaf(pk, vy, cx[2 * ql + 1]);
          }
        }
        float* cr = s_q + (ray * 8 + rb) * S_A;
        #pragma unroll
        for (int ql = 0; ql < 4; ql++) {
          cr[ql * S_A + lane] = cx[2 * ql];
          cr[ql * S_A + lane + 32] = cx[2 * ql + 1];
        }
      }
      __syncthreads();   // (B) ctx + staged weights visible

      // out-proj: co += ctx @ Wo_h
      gemm_acc(s_q, s_w3, lane, mt, nq, co);
      // no sync: next head's stores hit q/k/v post sync-A(h+1); w3 readers done
    }  // heads

    store_c(s_ao, lane, mt, nq, co, p.bo + l * 64, 0, nullptr);
    __syncthreads();
    // LN1: act = LN(ao + act)
    ln4(s_ao + (ray * 8 + rb) * S_A, s_act + (ray * 8 + rb) * S_A,
        p.g1 + l * 64, p.be1 + l * 64, lane, s_act + (ray * 8 + rb) * S_A);
    __syncthreads();
    // FF1 (w0 = fW1 staged during h==3) -> s_q with relu
    {
      float c[2][4] = {};
      gemm_acc(s_act, s_w0, lane, mt, nq, c);
      store_c(s_q, lane, mt, nq, c, p.fb1 + l * 64, 1, nullptr);
    }
    __syncthreads();
    // FF2 + residual -> ao
    {
      float c[2][4] = {};
      gemm_acc(s_q, s_w1, lane, mt, nq, c);
      store_c(s_ao, lane, mt, nq, c, p.fb2 + l * 64, 0, s_act);
    }
    __syncthreads();
    // LN2: act = LN(ao)
    ln4(s_ao + (ray * 8 + rb) * S_A, nullptr,
        p.g2 + l * 64, p.be2 + l * 64, lane, s_act + (ray * 8 + rb) * S_A);
    __syncthreads();
  }  // layers

  // ---------------- sigma & out ----------------
  {
    const float* ar = s_act + ray * 8 * S_A;
    if (half == 0) {
      float m0 = ar[lane], m1 = ar[lane + 32];
      #pragma unroll
      for (int s = 1; s < 8; s++) {
        m0 = fmaxf(m0, ar[s * S_A + lane]);
        m1 = fmaxf(m1, ar[s * S_A + lane + 32]);
      }
      float part = m0 * __ldg(p.Ws + lane) + m1 * __ldg(p.Ws + lane + 32);
      #pragma unroll
      for (int o = 16; o > 0; o >>= 1) part += __shfl_xor_sync(0xffffffffu, part, o);
      if (lane == 0) p.o_sigma[b] = part + __ldg(p.bs);
    }
    #pragma unroll
    for (int s = 0; s < 4; s++) {
      p.o_out[(size_t)b * 512 + (rb + s) * 64 + lane] = ar[(rb + s) * S_A + lane];
      p.o_out[(size_t)b * 512 + (rb + s) * 64 + lane + 32] =
          ar[(rb + s) * S_A + lane + 32];
    }
  }

  // ---------------- cross attention + color ----------------
  float* qr = s_ao + ray * S_A;  // query row (fp32)
  if (half == 0) {
    qr[lane] = p.query[(size_t)b * 64 + lane];
    qr[lane + 32] = p.query[(size_t)b * 64 + lane + 32];
  }

  float ca0 = 0.f, ca1 = 0.f;
  for (int h = 0; h < 4; h++) {
    __syncthreads();   // protect weight bufs from previous head's readers
    stage_w_il(p.cWk + h * 64, 256, s_w0, tid);
    stage_w_il(p.cWv + h * 64, 256, s_w1, tid);
    stage_w_il(p.cWq + h * 64, 256, s_w3, tid);
    stage_w_il(p.cWo + h * 4096, 64, s_w2, tid);
    __syncthreads();
    // fused cK, cV gemms
    {
      float ck[2][4] = {}, cv[2][4] = {};
      gemm2_acc(s_act, s_w0, s_w1, lane, mt, nq, ck, cv);
      store_c(s_k, lane, mt, nq, ck, p.cbk + h * 64, 0, nullptr);
      store_c(s_v, lane, mt, nq, cv, p.cbv + h * 64, 0, nullptr);
    }
    __syncthreads();
    // per-ray scalar on warps 0-7 (il weights reconstructed as hi+lo)
    if (half == 0) {
      float cq0 = __ldg(p.cbq + h * 64 + lane);
      float cq1 = __ldg(p.cbq + h * 64 + lane + 32);
      #pragma unroll 8
      for (int k = 0; k < 64; k++) {
        float a = qr[k];
        float2 w0 = *(const float2*)(s_w3 + k * S_WI + lane * 2);
        float2 w1 = *(const float2*)(s_w3 + k * S_WI + (lane + 32) * 2);
        cq0 = fmaf(a, w0.x + w0.y, cq0);
        cq1 = fmaf(a, w1.x + w1.y, cq1);
      }
      const float* kb = s_k + ray * 8 * S_A;
      const float* vb = s_v + ray * 8 * S_A;
      float e[8];
      #pragma unroll
      for (int k = 0; k < 8; k++) {
        float pk = cq0 * kb[k * S_A + lane] + cq1 * kb[k * S_A + lane + 32];
        #pragma unroll
        for (int o = 16; o > 0; o >>= 1) pk += __shfl_xor_sync(0xffffffffu, pk, o);
        e[k] = pk * 0.125f;
      }
      float mm = e[0];
      #pragma unroll
      for (int k = 1; k < 8; k++) mm = fmaxf(mm, e[k]);
      float prb[8], sum = 0.f;
      #pragma unroll
      for (int k = 0; k < 8; k++) { prb[k] = __expf(e[k] - mm); sum += prb[k]; }
      float inv = __fdividef(1.f, sum);
      float cx0 = 0.f, cx1 = 0.f;
      #pragma unroll
      for (int k = 0; k < 8; k++) {
        float pk = prb[k] * inv;
        cx0 = fmaf(pk, vb[k * S_A + lane], cx0);
        cx1 = fmaf(pk, vb[k * S_A + lane + 32], cx1);
      }
      my_p[lane] = cx0;
      my_p[lane + 32] = cx1;
      __syncwarp();
      if (h == 0) { ca0 = __ldg(p.cbo + lane); ca1 = __ldg(p.cbo + lane + 32); }
      #pragma unroll 8
      for (int k = 0; k < 64; k++) {
        float a = my_p[k];
        float2 w0 = *(const float2*)(s_w2 + k * S_WI + lane * 2);
        float2 w1 = *(const float2*)(s_w2 + k * S_WI + (lane + 32) * 2);
        ca0 = fmaf(a, w0.x + w0.y, ca0);
        ca1 = fmaf(a, w1.x + w1.y, ca1);
      }
    }
  }

  // color = relu(ca) @ Wc + bc (warps 0-7)
  if (half == 0) {
    float r0 = fmaxf(ca0, 0.f), r1 = fmaxf(ca1, 0.f);
    #pragma unroll
    for (int t = 0; t < 3; t++) {
      float part = r0 * __ldg(p.Wc + lane * 3 + t) + r1 * __ldg(p.Wc + (lane + 32) * 3 + t);
      #pragma unroll
      for (int o = 16; o > 0; o >>= 1) part += __shfl_xor_sync(0xffffffffu, part, o);
      if (lane == 0) p.o_color[(size_t)b * 3 + t] = part + __ldg(p.bc + t);
    }
  }
}

extern "C" void kernel_launch(void* const* d_in, const int* in_sizes, int n_in,
                              void* d_out, int out_size) {
  Params p;
  p.query = (const float*)d_in[0];
  p.latent = (const float*)d_in[1];
  p.W1 = (const float*)d_in[2];
  p.b1 = (const float*)d_in[3];
  p.Wq = (const float*)d_in[4];
  p.bq = (const float*)d_in[5];
  p.Wk = (const float*)d_in[6];
  p.bk = (const float*)d_in[7];
  p.Wv = (const float*)d_in[8];
  p.bv = (const float*)d_in[9];
  p.Wo = (const float*)d_in[10];
  p.bo = (const float*)d_in[11];
  p.fW1 = (const float*)d_in[12];
  p.fb1 = (const float*)d_in[13];
  p.fW2 = (const float*)d_in[14];
  p.fb2 = (const float*)d_in[15];
  p.g1 = (const float*)d_in[16];
  p.be1 = (const float*)d_in[17];
  p.g2 = (const float*)d_in[18];
  p.be2 = (const float*)d_in[19];
  p.cWq = (const float*)d_in[20];
  p.cbq = (const float*)d_in[21];
  p.cWk = (const float*)d_in[22];
  p.cbk = (const float*)d_in[23];
  p.cWv = (const float*)d_in[24];
  p.cbv = (const float*)d_in[25];
  p.cWo = (const float*)d_in[26];
  p.cbo = (const float*)d_in[27];
  p.Wc = (const float*)d_in[28];
  p.bc = (const float*)d_in[29];
  p.Ws = (const float*)d_in[30];
  p.bs = (const float*)d_in[31];

  float* o = (float*)d_out;
  p.o_color = o;                                    // [B,1,3]
  p.o_sigma = o + (size_t)B_TOTAL * 3;              // [B,1]
  p.o_out = o + (size_t)B_TOTAL * 4;                // [B,8,64]
  p.o_attn = o + (size_t)B_TOTAL * 4 + (size_t)B_TOTAL * 512;  // [B,4,4,8,8]

  cudaFuncSetAttribute(rt_kernel, cudaFuncAttributeMaxDynamicSharedMemorySize,
                       SMEM_BYTES);
  rt_kernel<<<NBLOCKS, NTHREADS, SMEM_BYTES>>>(p);
}

// round 13
// speedup vs baseline: 1.6232x; 1.5229x over previous
#include <cuda_runtime.h>
#include <cuda_fp16.h>

typedef unsigned long long ull;
typedef unsigned int uint;

#define NTHREADS 512
#define RAYS 8
#define NBLOCKS 4096
#define B_TOTAL 32768
#define S_A 68      // fp32 tile stride (floats): frag/scalar loads conflict-free
#define S_H 72      // half tile stride (halves): word stride 36 == 4 mod 32 -> conflict-free

// smem offsets (floats)
#define OFF_Q    0              // fp32 tiles 64x68 = 4352 each
#define OFF_K    4352
#define OFF_V    8704
#define OFF_AO   13056
#define OFF_ACTH 17408          // half tiles 64x72 halves = 2304 floats each
#define OFF_ACTL 19712
#define OFF_XH   22016          // ctx / FF1-out / latent-pong
#define OFF_XL   24320
#define OFF_W0H  26624          // weight half tiles [n][k]
#define OFF_W0L  28928
#define OFF_W1H  31232
#define OFF_W1L  33536
#define OFF_W2H  35840
#define OFF_W2L  38144
#define OFF_W3H  40448
#define OFF_W3L  42752
#define OFF_P    45056          // probs 8x64
#define SMEM_FLOATS (45056 + 512)   // 45568 floats = 182272 B
#define SMEM_BYTES (SMEM_FLOATS * 4)

struct Params {
  const float *query, *latent, *W1, *b1;
  const float *Wq, *bq, *Wk, *bk, *Wv, *bv, *Wo, *bo;
  const float *fW1, *fb1, *fW2, *fb2, *g1, *be1, *g2, *be2;
  const float *cWq, *cbq, *cWk, *cbk, *cWv, *cbv, *cWo, *cbo;
  const float *Wc, *bc, *Ws, *bs;
  float *o_color, *o_sigma, *o_out, *o_attn;
};

// ---------------- helpers ----------------
__device__ __forceinline__ ull ffma2(ull a, ull b, ull c) {
  ull d;
  asm("fma.rn.f32x2 %0, %1, %2, %3;" : "=l"(d) : "l"(a), "l"(b), "l"(c));
  return d;
}
__device__ __forceinline__ ull pack2(float lo, float hi) {
  ull d;
  asm("mov.b64 %0, {%1, %2};" : "=l"(d) : "f"(lo), "f"(hi));
  return d;
}
__device__ __forceinline__ float2 unpack2(ull v) {
  float lo, hi;
  asm("mov.b64 {%0, %1}, %2;" : "=f"(lo), "=f"(hi) : "l"(v));
  return make_float2(lo, hi);
}

// pack two floats to half2 (hi), returning residuals
__device__ __forceinline__ uint hpackr(float a, float b, float& ra, float& rb) {
  __half ha = __float2half_rn(a), hb = __float2half_rn(b);
  ra = a - __half2float(ha);
  rb = b - __half2float(hb);
  __half2 p = __halves2half2(ha, hb);
  return *(uint*)&p;
}
__device__ __forceinline__ uint hpack(float a, float b) {
  __half2 p = __halves2half2(__float2half_rn(a), __float2half_rn(b));
  return *(uint*)&p;
}
__device__ __forceinline__ float2 h2f(uint u) {
  return __half22float2(*(__half2*)&u);
}
// split one float to (h,l) halves
__device__ __forceinline__ void hsplit1(float x, __half& h, __half& l) {
  h = __float2half_rn(x);
  l = __float2half_rn(x - __half2float(h));
}

// m16n8k16 fp16 mma, fp32 accumulate, D=C in place
__device__ __forceinline__ void mma16(float c[4], uint a0, uint a1, uint a2, uint a3,
                                      uint b0, uint b1) {
  asm("mma.sync.aligned.m16n8k16.row.col.f32.f16.f16.f32 "
      "{%0,%1,%2,%3},{%4,%5,%6,%7},{%8,%9},{%0,%1,%2,%3};"
      : "+f"(c[0]), "+f"(c[1]), "+f"(c[2]), "+f"(c[3])
      : "r"(a0), "r"(a1), "r"(a2), "r"(a3), "r"(b0), "r"(b1));
}

struct AF { uint h[4], l[4]; };
// A fragment (k16 slab) from pre-split half tiles: 8x LDS.32, zero ALU
__device__ __forceinline__ AF load_a(const uint* __restrict__ Ah,
                                     const uint* __restrict__ Al,
                                     int lane, int mt, int kk) {
  const int grp = lane >> 2, kq = lane & 3;
  const int base = (mt * 16 + grp) * 36 + kk * 8 + kq;
  AF f;
  f.h[0] = Ah[base];
  f.h[1] = Ah[base + 8 * 36];
  f.h[2] = Ah[base + 4];
  f.h[3] = Ah[base + 8 * 36 + 4];
  f.l[0] = Al[base];
  f.l[1] = Al[base + 8 * 36];
  f.l[2] = Al[base + 4];
  f.l[3] = Al[base + 8 * 36 + 4];
  return f;
}

// 3xFP16 k16 step: c += a*w (drop lo*lo)
__device__ __forceinline__ void mma3h(float c[4], const AF& a,
                                      uint wh0, uint wh1, uint wl0, uint wl1) {
  mma16(c, a.h[0], a.h[1], a.h[2], a.h[3], wh0, wh1);
  mma16(c, a.l[0], a.l[1], a.l[2], a.l[3], wh0, wh1);
  mma16(c, a.h[0], a.h[1], a.h[2], a.h[3], wl0, wl1);
}

// Warp roles: mt = m-tile (16 rows), nq = n-quarter (16 cols)
__device__ __forceinline__ void gemm_acc(const uint* Ah, const uint* Al,
                                         const uint* Wh, const uint* Wl,
                                         int lane, int mt, int nq, float c[2][4]) {
  const int grp = lane >> 2, kq = lane & 3;
  #pragma unroll
  for (int kk = 0; kk < 4; kk++) {
    AF a = load_a(Ah, Al, lane, mt, kk);
    const int off = (nq * 16 + grp) * 36 + kk * 8 + kq;
    #pragma unroll
    for (int t = 0; t < 2; t++) {
      const int o = off + t * 8 * 36;
      mma3h(c[t], a, Wh[o], Wh[o + 4], Wl[o], Wl[o + 4]);
    }
  }
}

__device__ __forceinline__ void gemm3_acc(const uint* Ah, const uint* Al,
                                          const uint* W0h, const uint* W0l,
                                          const uint* W1h, const uint* W1l,
                                          const uint* W2h, const uint* W2l,
                                          int lane, int mt, int nq,
                                          float c0[2][4], float c1[2][4],
                                          float c2[2][4]) {
  const int grp = lane >> 2, kq = lane & 3;
  #pragma unroll
  for (int kk = 0; kk < 4; kk++) {
    AF a = load_a(Ah, Al, lane, mt, kk);
    const int off = (nq * 16 + grp) * 36 + kk * 8 + kq;
    #pragma unroll
    for (int t = 0; t < 2; t++) {
      const int o = off + t * 8 * 36;
      mma3h(c0[t], a, W0h[o], W0h[o + 4], W0l[o], W0l[o + 4]);
      mma3h(c1[t], a, W1h[o], W1h[o + 4], W1l[o], W1l[o + 4]);
      mma3h(c2[t], a, W2h[o], W2h[o + 4], W2l[o], W2l[o + 4]);
    }
  }
}

__device__ __forceinline__ void gemm2_acc(const uint* Ah, const uint* Al,
                                          const uint* W0h, const uint* W0l,
                                          const uint* W1h, const uint* W1l,
                                          int lane, int mt, int nq,
                                          float c0[2][4], float c1[2][4]) {
  const int grp = lane >> 2, kq = lane & 3;
  #pragma unroll
  for (int kk = 0; kk < 4; kk++) {
    AF a = load_a(Ah, Al, lane, mt, kk);
    const int off = (nq * 16 + grp) * 36 + kk * 8 + kq;
    #pragma unroll
    for (int t = 0; t < 2; t++) {
      const int o = off + t * 8 * 36;
      mma3h(c0[t], a, W0h[o], W0h[o + 4], W0l[o], W0l[o + 4]);
      mma3h(c1[t], a, W1h[o], W1h[o + 4], W1l[o], W1l[o + 4]);
    }
  }
}

// store C frags to plain fp32 tile; optional relu / residual from HALF tiles
__device__ __forceinline__ void store_c(float* D, int lane, int mt, int nq,
                                        const float c[2][4], const float* bias,
                                        int do_relu, const uint* rh, const uint* rl) {
  const int grp = lane >> 2, kq = lane & 3;
  const int r = mt * 16 + grp;
  #pragma unroll
  for (int t = 0; t < 2; t++) {
    int col = nq * 16 + t * 8 + 2 * kq;
    float b0 = __ldg(bias + col), b1 = __ldg(bias + col + 1);
    float v0 = c[t][0] + b0, v1 = c[t][1] + b1;
    float v2 = c[t][2] + b0, v3 = c[t][3] + b1;
    if (rh) {
      int w0 = r * 36 + (col >> 1), w1 = (r + 8) * 36 + (col >> 1);
      float2 fh0 = h2f(rh[w0]), fl0 = h2f(rl[w0]);
      float2 fh1 = h2f(rh[w1]), fl1 = h2f(rl[w1]);
      v0 += fh0.x + fl0.x; v1 += fh0.y + fl0.y;
      v2 += fh1.x + fl1.x; v3 += fh1.y + fl1.y;
    }
    if (do_relu) {
      v0 = fmaxf(v0, 0.f); v1 = fmaxf(v1, 0.f);
      v2 = fmaxf(v2, 0.f); v3 = fmaxf(v3, 0.f);
    }
    *(float2*)(D + r * S_A + col) = make_float2(v0, v1);
    *(float2*)(D + (r + 8) * S_A + col) = make_float2(v2, v3);
  }
}

// store C frags SPLIT into half hi/lo tiles (gemm-input format)
__device__ __forceinline__ void store_c_h(uint* Dh, uint* Dl, int lane, int mt, int nq,
                                          const float c[2][4], const float* bias,
                                          int do_relu) {
  const int grp = lane >> 2, kq = lane & 3;
  const int r = mt * 16 + grp;
  #pragma unroll
  for (int t = 0; t < 2; t++) {
    int col = nq * 16 + t * 8 + 2 * kq;
    float b0 = __ldg(bias + col), b1 = __ldg(bias + col + 1);
    float v0 = c[t][0] + b0, v1 = c[t][1] + b1;
    float v2 = c[t][2] + b0, v3 = c[t][3] + b1;
    if (do_relu) {
      v0 = fmaxf(v0, 0.f); v1 = fmaxf(v1, 0.f);
      v2 = fmaxf(v2, 0.f); v3 = fmaxf(v3, 0.f);
    }
    float ra, rb;
    uint h01 = hpackr(v0, v1, ra, rb);
    uint l01 = hpack(ra, rb);
    Dh[r * 36 + (col >> 1)] = h01;
    Dl[r * 36 + (col >> 1)] = l01;
    uint h23 = hpackr(v2, v3, ra, rb);
    uint l23 = hpack(ra, rb);
    Dh[(r + 8) * 36 + (col >> 1)] = h23;
    Dl[(r + 8) * 36 + (col >> 1)] = l23;
  }
}

// stage 64x64 weight block: transpose to [n][k] and split to half hi/lo tiles
__device__ __forceinline__ void stage_w_h(const float* __restrict__ src, int stride,
                                          __half* __restrict__ dh,
                                          __half* __restrict__ dl, int tid) {
  #pragma unroll
  for (int it = 0; it < 2; it++) {
    int i = tid + it * NTHREADS;
    int n = i & 63, k4 = (i >> 6) << 2;
    float v0 = src[(k4 + 0) * stride + n];
    float v1 = src[(k4 + 1) * stride + n];
    float v2 = src[(k4 + 2) * stride + n];
    float v3 = src[(k4 + 3) * stride + n];
    float r0, r1, r2, r3;
    uint2 hw, lw;
    hw.x = hpackr(v0, v1, r0, r1);
    hw.y = hpackr(v2, v3, r2, r3);
    lw.x = hpack(r0, r1);
    lw.y = hpack(r2, r3);
    *(uint2*)(dh + n * S_H + k4) = hw;
    *(uint2*)(dl + n * S_H + k4) = lw;
  }
}

// LayerNorm of 4 rows: s1 fp32 tile (+ optional residual from half tiles), dst half tiles
__device__ __forceinline__ void ln4(const float* s1, const __half* s2h,
                                    const __half* s2l, const float* g,
                                    const float* be, int lane,
                                    __half* dh, __half* dl) {
  float gg0 = __ldg(g + lane), gg1 = __ldg(g + lane + 32);
  float bb0 = __ldg(be + lane), bb1 = __ldg(be + lane + 32);
  #pragma unroll
  for (int s = 0; s < 4; s++) {
    float x0 = s1[s * S_A + lane];
    float x1 = s1[s * S_A + lane + 32];
    if (s2h) {
      x0 += __half2float(s2h[s * S_H + lane]) + __half2float(s2l[s * S_H + lane]);
      x1 += __half2float(s2h[s * S_H + lane + 32]) + __half2float(s2l[s * S_H + lane + 32]);
    }
    float sum = x0 + x1;
    #pragma unroll
    for (int o = 16; o > 0; o >>= 1) sum += __shfl_xor_sync(0xffffffffu, sum, o);
    float mean = sum * 0.015625f;
    float d0 = x0 - mean, d1 = x1 - mean;
    float vs = d0 * d0 + d1 * d1;
    #pragma unroll
    for (int o = 16; o > 0; o >>= 1) vs += __shfl_xor_sync(0xffffffffu, vs, o);
    float rstd = rsqrtf(vs * 0.015625f + 1e-5f);
    float y0 = d0 * rstd * gg0 + bb0;
    float y1 = d1 * rstd * gg1 + bb1;
    __half h, l;
    hsplit1(y0, h, l);
    dh[s * S_H + lane] = h; dl[s * S_H + lane] = l;
    hsplit1(y1, h, l);
    dh[s * S_H + lane + 32] = h; dl[s * S_H + lane + 32] = l;
  }
}

// stage a latent chunk split into half hi/lo tiles
#define STAGE_LAT(DH, DL, KC)                                                  \
  do {                                                                         \
    _Pragma("unroll")                                                          \
    for (int it_ = 0; it_ < 2; it_++) {                                        \
      int i_ = tid + it_ * NTHREADS;                                           \
      int row_ = i_ >> 4, j_ = (i_ & 15) * 4;                                  \
      float4 v_ = *(const float4*)(p.latent + (size_t)(bbase + (row_ >> 3)) * 4096 + \
                                   (row_ & 7) * 512 + (KC) * 64 + j_);         \
      float r0_, r1_, r2_, r3_;                                                \
      uint2 hw_, lw_;                                                          \
      hw_.x = hpackr(v_.x, v_.y, r0_, r1_);                                    \
      hw_.y = hpackr(v_.z, v_.w, r2_, r3_);                                    \
      lw_.x = hpack(r0_, r1_);                                                 \
      lw_.y = hpack(r2_, r3_);                                                 \
      *(uint2*)((DH) + row_ * S_H + j_) = hw_;                                 \
      *(uint2*)((DL) + row_ * S_H + j_) = lw_;                                 \
    }                                                                          \
  } while (0)

__global__ void __launch_bounds__(NTHREADS, 1) rt_kernel(Params p) {
  extern __shared__ float sm[];
  const int tid = threadIdx.x;
  const int warp = tid >> 5, lane = tid & 31;
  const int mt = warp & 3, nq = warp >> 2;   // mma roles (4 x 4)
  const int ray = warp & 7, half_ = warp >> 3, rb = half_ * 4;  // scalar roles
  const int bbase = blockIdx.x * RAYS;
  const int b = bbase + ray;

  float* s_q = sm + OFF_Q;      // fp32
  float* s_k = sm + OFF_K;
  float* s_v = sm + OFF_V;
  float* s_ao = sm + OFF_AO;
  __half* acth = (__half*)(sm + OFF_ACTH);
  __half* actl = (__half*)(sm + OFF_ACTL);
  __half* xh = (__half*)(sm + OFF_XH);
  __half* xl = (__half*)(sm + OFF_XL);
  uint* uacth = (uint*)acth;
  uint* uactl = (uint*)actl;
  uint* uxh = (uint*)xh;
  uint* uxl = (uint*)xl;
  uint* w0h = (uint*)(sm + OFF_W0H); uint* w0l = (uint*)(sm + OFF_W0L);
  uint* w1h = (uint*)(sm + OFF_W1H); uint* w1l = (uint*)(sm + OFF_W1L);
  uint* w2h = (uint*)(sm + OFF_W2H); uint* w2l = (uint*)(sm + OFF_W2L);
  uint* w3h = (uint*)(sm + OFF_W3H); uint* w3l = (uint*)(sm + OFF_W3L);
  float* my_p = sm + OFF_P + ray * 64;

  // ---------------- stage 0: act = relu(latent @ W1 + b1), K=512 ----------------
  {
    stage_w_h(p.W1, 64, (__half*)w0h, (__half*)w0l, tid);
    STAGE_LAT(acth, actl, 0);
    __syncthreads();
    float c[2][4] = {};
    for (int kc = 0; kc < 8; kc++) {
      const uint* lbh = (kc & 1) ? uxh : uacth;
      const uint* lbl = (kc & 1) ? uxl : uactl;
      const uint* wbh = (kc & 1) ? w1h : w0h;
      const uint* wbl = (kc & 1) ? w1l : w0l;
      if (kc < 7) {
        stage_w_h(p.W1 + (kc + 1) * 4096, 64,
                  (kc & 1) ? (__half*)w0h : (__half*)w1h,
                  (kc & 1) ? (__half*)w0l : (__half*)w1l, tid);
        if (kc & 1) STAGE_LAT(acth, actl, kc + 1);
        else        STAGE_LAT(xh, xl, kc + 1);
      }
      gemm_acc(lbh, lbl, wbh, wbl, lane, mt, nq, c);
      __syncthreads();
    }
    store_c_h(uacth, uactl, lane, mt, nq, c, p.b1, 1);
  }
  __syncthreads();

  // ---------------- 4 transformer layers ----------------
  for (int l = 0; l < 4; l++) {
    stage_w_h(p.Wq + l * 16384, 256, (__half*)w0h, (__half*)w0l, tid);
    stage_w_h(p.Wk + l * 16384, 256, (__half*)w1h, (__half*)w1l, tid);
    stage_w_h(p.Wv + l * 16384, 256, (__half*)w2h, (__half*)w2l, tid);
    __syncthreads();

    float co[2][4] = {};   // out-proj accumulator across heads
    for (int h = 0; h < 4; h++) {
      // fused QKV (one A pass, pre-split everything)
      {
        float cq[2][4] = {}, ck[2][4] = {}, cv[2][4] = {};
        gemm3_acc(uacth, uactl, w0h, w0l, w1h, w1l, w2h, w2l,
                  lane, mt, nq, cq, ck, cv);
        store_c(s_q, lane, mt, nq, cq, p.bq + l * 256 + h * 64, 0, nullptr, nullptr);
        store_c(s_k, lane, mt, nq, ck, p.bk + l * 256 + h * 64, 0, nullptr, nullptr);
        store_c(s_v, lane, mt, nq, cv, p.bv + l * 256 + h * 64, 0, nullptr, nullptr);
      }
      __syncthreads();   // (A) QKV visible

      // stage next weights; LDG latency overlapped by attention below
      stage_w_h(p.Wo + l * 16384 + h * 4096, 64, (__half*)w3h, (__half*)w3l, tid);
      if (h < 3) {
        stage_w_h(p.Wq + l * 16384 + (h + 1) * 64, 256, (__half*)w0h, (__half*)w0l, tid);
        stage_w_h(p.Wk + l * 16384 + (h + 1) * 64, 256, (__half*)w1h, (__half*)w1l, tid);
        stage_w_h(p.Wv + l * 16384 + (h + 1) * 64, 256, (__half*)w2h, (__half*)w2l, tid);
      } else {
        stage_w_h(p.fW1 + l * 4096, 64, (__half*)w0h, (__half*)w0l, tid);
        stage_w_h(p.fW2 + l * 4096, 64, (__half*)w1h, (__half*)w1l, tid);
      }

      // ---- attention (scalar fp32): warp pair per ray, 4 q-rows each ----
      {
        const float* qb = s_q + ray * 8 * S_A;
        const float* kb = s_k + ray * 8 * S_A;
        const float* vb = s_v + ray * 8 * S_A;
        int idx = half_ * 32 + lane;
        int qi = idx >> 3, ki = idx & 7;
        const float* qr = qb + qi * S_A;
        const float* kr = kb + ki * S_A;
        ull acc = pack2(0.f, 0.f);
        #pragma unroll
        for (int j = 0; j < 64; j += 4) {
          ulonglong2 qq = *(const ulonglong2*)(qr + j);
          ulonglong2 kk2 = *(const ulonglong2*)(kr + j);
          acc = ffma2(qq.x, kk2.x, acc);
          acc = ffma2(qq.y, kk2.y, acc);
        }
        float2 t = unpack2(acc);
        float sc = (t.x + t.y) * 0.125f;
        float m = sc;
        m = fmaxf(m, __shfl_xor_sync(0xffffffffu, m, 1));
        m = fmaxf(m, __shfl_xor_sync(0xffffffffu, m, 2));
        m = fmaxf(m, __shfl_xor_sync(0xffffffffu, m, 4));
        float e = __expf(sc - m);
        float se = e;
        se += __shfl_xor_sync(0xffffffffu, se, 1);
        se += __shfl_xor_sync(0xffffffffu, se, 2);
        se += __shfl_xor_sync(0xffffffffu, se, 4);
        float pr = __fdividef(e, se);
        my_p[idx] = pr;
        p.o_attn[(size_t)b * 1024 + (size_t)l * 256 + h * 64 + idx] = pr;
        __syncwarp();
        // ctx rows rb..rb+3 = P @ V -> split into x half tiles
        float cx[8];
        #pragma unroll
        for (int i = 0; i < 8; i++) cx[i] = 0.f;
        #pragma unroll
        for (int kj = 0; kj < 8; kj++) {
          float vx = vb[kj * S_A + lane];
          float vy = vb[kj * S_A + lane + 32];
          #pragma unroll
          for (int ql = 0; ql < 4; ql++) {
            float pk = my_p[(rb + ql) * 8 + kj];
            cx[2 * ql] = fmaf(pk, vx, cx[2 * ql]);
            cx[2 * ql + 1] = fmaf(pk, vy, cx[2 * ql + 1]);
          }
        }
        #pragma unroll
        for (int ql = 0; ql < 4; ql++) {
          int row = ray * 8 + rb + ql;
          __half hh, hl;
          hsplit1(cx[2 * ql], hh, hl);
          xh[row * S_H + lane] = hh; xl[row * S_H + lane] = hl;
          hsplit1(cx[2 * ql + 1], hh, hl);
          xh[row * S_H + lane + 32] = hh; xl[row * S_H + lane + 32] = hl;
        }
      }
      __syncthreads();   // (B) ctx + staged weights visible

      // out-proj: co += ctx @ Wo_h  (x readers finish before sync-A of h+1)
      gemm_acc(uxh, uxl, w3h, w3l, lane, mt, nq, co);
    }  // heads

    store_c(s_ao, lane, mt, nq, co, p.bo + l * 64, 0, nullptr, nullptr);
    __syncthreads();
    // LN1: act = LN(ao + act)
    ln4(s_ao + (ray * 8 + rb) * S_A,
        acth + (ray * 8 + rb) * S_H, actl + (ray * 8 + rb) * S_H,
        p.g1 + l * 64, p.be1 + l * 64, lane,
        acth + (ray * 8 + rb) * S_H, actl + (ray * 8 + rb) * S_H);
    __syncthreads();
    // FF1 (w0 = fW1 staged during h==3) -> x half tiles with relu
    {
      float c[2][4] = {};
      gemm_acc(uacth, uactl, w0h, w0l, lane, mt, nq, c);
      store_c_h(uxh, uxl, lane, mt, nq, c, p.fb1 + l * 64, 1);
    }
    __syncthreads();
    // FF2 + residual(act halves) -> ao fp32
    {
      float c[2][4] = {};
      gemm_acc(uxh, uxl, w1h, w1l, lane, mt, nq, c);
      store_c(s_ao, lane, mt, nq, c, p.fb2 + l * 64, 0, uacth, uactl);
    }
    __syncthreads();
    // LN2: act = LN(ao)
    ln4(s_ao + (ray * 8 + rb) * S_A, nullptr, nullptr,
        p.g2 + l * 64, p.be2 + l * 64, lane,
        acth + (ray * 8 + rb) * S_H, actl + (ray * 8 + rb) * S_H);
    __syncthreads();
  }  // layers

  // ---------------- sigma & out ----------------
  {
    const __half* ah = acth + ray * 8 * S_H;
    const __half* al = actl + ray * 8 * S_H;
    if (half_ == 0) {
      float m0 = -1e30f, m1 = -1e30f;
      #pragma unroll
      for (int s = 0; s < 8; s++) {
        m0 = fmaxf(m0, __half2float(ah[s * S_H + lane]) + __half2float(al[s * S_H + lane]));
        m1 = fmaxf(m1, __half2float(ah[s * S_H + lane + 32]) + __half2float(al[s * S_H + lane + 32]));
      }
      float part = m0 * __ldg(p.Ws + lane) + m1 * __ldg(p.Ws + lane + 32);
      #pragma unroll
      for (int o = 16; o > 0; o >>= 1) part += __shfl_xor_sync(0xffffffffu, part, o);
      if (lane == 0) p.o_sigma[b] = part + __ldg(p.bs);
    }
    #pragma unroll
    for (int s = 0; s < 4; s++) {
      int row = rb + s;
      p.o_out[(size_t)b * 512 + row * 64 + lane] =
          __half2float(ah[row * S_H + lane]) + __half2float(al[row * S_H + lane]);
      p.o_out[(size_t)b * 512 + row * 64 + lane + 32] =
          __half2float(ah[row * S_H + lane + 32]) + __half2float(al[row * S_H + lane + 32]);
    }
  }

  // ---------------- cross attention + color ----------------
  float* qr = s_ao + ray * S_A;  // query row (fp32)
  if (half_ == 0) {
    qr[lane] = p.query[(size_t)b * 64 + lane];
    qr[lane + 32] = p.query[(size_t)b * 64 + lane + 32];
  }

  float ca0 = 0.f, ca1 = 0.f;
  for (int h = 0; h < 4; h++) {
    __syncthreads();   // protect weight bufs from previous head's readers
    stage_w_h(p.cWk + h * 64, 256, (__half*)w0h, (__half*)w0l, tid);
    stage_w_h(p.cWv + h * 64, 256, (__half*)w1h, (__half*)w1l, tid);
    stage_w_h(p.cWq + h * 64, 256, (__half*)w3h, (__half*)w3l, tid);
    stage_w_h(p.cWo + h * 4096, 64, (__half*)w2h, (__half*)w2l, tid);
    __syncthreads();
    // fused cK, cV gemms
    {
      float ck[2][4] = {}, cv[2][4] = {};
      gemm2_acc(uacth, uactl, w0h, w0l, w1h, w1l, lane, mt, nq, ck, cv);
      store_c(s_k, lane, mt, nq, ck, p.cbk + h * 64, 0, nullptr, nullptr);
      store_c(s_v, lane, mt, nq, cv, p.cbv + h * 64, 0, nullptr, nullptr);
    }
    __syncthreads();
    // per-ray scalar on warps 0-7 (weights reconstructed hi+lo from [n][k] half tiles)
    if (half_ == 0) {
      float cq0 = __ldg(p.cbq + h * 64 + lane);
      float cq1 = __ldg(p.cbq + h * 64 + lane + 32);
      #pragma unroll 8
      for (int k = 0; k < 64; k += 2) {
        int wi = k >> 1;
        float a0 = qr[k], a1 = qr[k + 1];
        float2 wv0 = h2f(w3h[lane * 36 + wi]);
        float2 wl0_ = h2f(w3l[lane * 36 + wi]);
        float2 wv1 = h2f(w3h[(lane + 32) * 36 + wi]);
        float2 wl1_ = h2f(w3l[(lane + 32) * 36 + wi]);
        cq0 = fmaf(a0, wv0.x + wl0_.x, cq0);
        cq0 = fmaf(a1, wv0.y + wl0_.y, cq0);
        cq1 = fmaf(a0, wv1.x + wl1_.x, cq1);
        cq1 = fmaf(a1, wv1.y + wl1_.y, cq1);
      }
      const float* kb = s_k + ray * 8 * S_A;
      const float* vb = s_v + ray * 8 * S_A;
      float e[8];
      #pragma unroll
      for (int k = 0; k < 8; k++) {
        float pk = cq0 * kb[k * S_A + lane] + cq1 * kb[k * S_A + lane + 32];
        #pragma unroll
        for (int o = 16; o > 0; o >>= 1) pk += __shfl_xor_sync(0xffffffffu, pk, o);
        e[k] = pk * 0.125f;
      }
      float mm = e[0];
      #pragma unroll
      for (int k = 1; k < 8; k++) mm = fmaxf(mm, e[k]);
      float prb[8], sum = 0.f;
      #pragma unroll
      for (int k = 0; k < 8; k++) { prb[k] = __expf(e[k] - mm); sum += prb[k]; }
      float inv = __fdividef(1.f, sum);
      float cx0 = 0.f, cx1 = 0.f;
      #pragma unroll
      for (int k = 0; k < 8; k++) {
        float pk = prb[k] * inv;
        cx0 = fmaf(pk, vb[k * S_A + lane], cx0);
        cx1 = fmaf(pk, vb[k * S_A + lane + 32], cx1);
      }
      my_p[lane] = cx0;
      my_p[lane + 32] = cx1;
      __syncwarp();
      if (h == 0) { ca0 = __ldg(p.cbo + lane); ca1 = __ldg(p.cbo + lane + 32); }
      #pragma unroll 8
      for (int k = 0; k < 64; k += 2) {
        int wi = k >> 1;
        float a0 = my_p[k], a1 = my_p[k + 1];
        float2 wv0 = h2f(w2h[lane * 36 + wi]);
        float2 wl0_ = h2f(w2l[lane * 36 + wi]);
        float2 wv1 = h2f(w2h[(lane + 32) * 36 + wi]);
        float2 wl1_ = h2f(w2l[(lane + 32) * 36 + wi]);
        ca0 = fmaf(a0, wv0.x + wl0_.x, ca0);
        ca0 = fmaf(a1, wv0.y + wl0_.y, ca0);
        ca1 = fmaf(a0, wv1.x + wl1_.x, ca1);
        ca1 = fmaf(a1, wv1.y + wl1_.y, ca1);
      }
    }
  }

  // color = relu(ca) @ Wc + bc (warps 0-7)
  if (half_ == 0) {
    float r0 = fmaxf(ca0, 0.f), r1 = fmaxf(ca1, 0.f);
    #pragma unroll
    for (int t = 0; t < 3; t++) {
      float part = r0 * __ldg(p.Wc + lane * 3 + t) + r1 * __ldg(p.Wc + (lane + 32) * 3 + t);
      #pragma unroll
      for (int o = 16; o > 0; o >>= 1) part += __shfl_xor_sync(0xffffffffu, part, o);
      if (lane == 0) p.o_color[(size_t)b * 3 + t] = part + __ldg(p.bc + t);
    }
  }
}

extern "C" void kernel_launch(void* const* d_in, const int* in_sizes, int n_in,
                              void* d_out, int out_size) {
  Params p;
  p.query = (const float*)d_in[0];
  p.latent = (const float*)d_in[1];
  p.W1 = (const float*)d_in[2];
  p.b1 = (const float*)d_in[3];
  p.Wq = (const float*)d_in[4];
  p.bq = (const float*)d_in[5];
  p.Wk = (const float*)d_in[6];
  p.bk = (const float*)d_in[7];
  p.Wv = (const float*)d_in[8];
  p.bv = (const float*)d_in[9];
  p.Wo = (const float*)d_in[10];
  p.bo = (const float*)d_in[11];
  p.fW1 = (const float*)d_in[12];
  p.fb1 = (const float*)d_in[13];
  p.fW2 = (const float*)d_in[14];
  p.fb2 = (const float*)d_in[15];
  p.g1 = (const float*)d_in[16];
  p.be1 = (const float*)d_in[17];
  p.g2 = (const float*)d_in[18];
  p.be2 = (const float*)d_in[19];
  p.cWq = (const float*)d_in[20];
  p.cbq = (const float*)d_in[21];
  p.cWk = (const float*)d_in[22];
  p.cbk = (const float*)d_in[23];
  p.cWv = (const float*)d_in[24];
  p.cbv = (const float*)d_in[25];
  p.cWo = (const float*)d_in[26];
  p.cbo = (const float*)d_in[27];
  p.Wc = (const float*)d_in[28];
  p.bc = (const float*)d_in[29];
  p.Ws = (const float*)d_in[30];
  p.bs = (const float*)d_in[31];

  float* o = (float*)d_out;
  p.o_color = o;                                    // [B,1,3]
  p.o_sigma = o + (size_t)B_TOTAL * 3;              // [B,1]
  p.o_out = o + (size_t)B_TOTAL * 4;                // [B,8,64]
  p.o_attn = o + (size_t)B_TOTAL * 4 + (size_t)B_TOTAL * 512;  // [B,4,4,8,8]

  cudaFuncSetAttribute(rt_kernel, cudaFuncAttributeMaxDynamicSharedMemorySize,
                       SMEM_BYTES);
  rt_kernel<<<NBLOCKS, NTHREADS, SMEM_BYTES>>>(p);
}